// round 6
// baseline (speedup 1.0000x reference)
#include <cuda_runtime.h>
#include <cuda_bf16.h>
#include <cstdint>

// Problem constants
#define B_    64
#define C_    2048
#define HW_   192             // 24 * 8
#define HW4_  48              // HW_/4 float4s per row
#define GSUB  4               // CTAs per batch sample
#define CSLICE (C_ / GSUB)    // 512 channels per CTA
#define CSUB  8               // c-lanes per CTA
#define NTHR  (CSUB * HW4_)   // 384 threads
#define KITER (CSLICE / CSUB) // 64 c-iterations per thread
#define NUM_IDS_ 751

// Scratch (__device__ globals are zero-initialized; no allocation allowed)
__device__ float g_part[B_ * GSUB * HW_];   // per-(b,sub) partial heat (192 KB)
__device__ int   g_cnt[B_];                 // monotonic arrival counters

// ---------------------------------------------------------------------------
// pid loader: pids buffer may be int32 (64 ints) or int64 (64 longs).
// Only the first 64 int32 words are read (256 B, safe under both layouts).
// int64 layout => odd words all 0 (values < 751); int32 => odd words random.
// ---------------------------------------------------------------------------
__device__ __forceinline__ int load_pid(const int* __restrict__ p32, int b)
{
    bool odd_all_zero = true;
    bool any_nonzero  = false;
    #pragma unroll
    for (int i = 0; i < 64; i += 2) {
        if (p32[i + 1] != 0) odd_all_zero = false;
        if (p32[i]     != 0) any_nonzero = true;
    }
    const bool is64 = odd_all_zero && any_nonzero;
    int pid = is64 ? p32[2 * b] : p32[b];
    if (pid < 0) pid = 0;
    if (pid >= NUM_IDS_) pid = NUM_IDS_ - 1;
    return pid;
}

// ---------------------------------------------------------------------------
// Fused kernel, no clusters. grid = B_*GSUB = 256 CTAs, block = 384.
// Group of 4 CTAs per b; group barrier via L2 atomics with a monotonic
// ticket (graph-replay safe: no counter reset needed).
//   Pass 1: partial heat over own 512 channels -> g_part, arrive.
//   Barrier: spin until all 4 partials of this b are visible.
//   Pass 2: sum 4 partials, normalize (redundant per CTA), scale own slice.
//           Re-reads use __ldcs, writes use __stcs so the L2-resident copy of
//           f (100 MB < 126 MB L2) is not evicted by the output stream.
// ---------------------------------------------------------------------------
__global__ void __launch_bounds__(NTHR)
fused_kernel(const float4* __restrict__ f4,
             const float*  __restrict__ w,
             const int*    __restrict__ pids32,
             float4*       __restrict__ out4)
{
    const int b   = blockIdx.x >> 2;
    const int sub = blockIdx.x & 3;
    const int tid = threadIdx.x;
    const int c_sub = tid / HW4_;   // 0..7
    const int q     = tid % HW4_;   // 0..47

    __shared__ float  ws[CSLICE];       // weight slice (2 KB)
    __shared__ float4 sred[NTHR];       // c-lane partials (6 KB)
    __shared__ float  smn[12], smx[12], s_bmn, s_bmx;
    __shared__ int    s_pid, s_target;

    if (tid == 0)
        s_pid = load_pid(pids32, b);
    __syncthreads();

    const int c0 = sub * CSLICE;
    {
        const float* wrow = w + (size_t)s_pid * C_ + c0;
        for (int i = tid; i < CSLICE; i += NTHR)
            ws[i] = wrow[i];
    }
    __syncthreads();

    // ---------------- Pass 1: partial heat over own 512 channels -----------
    const size_t base = ((size_t)b * C_ + c0 + c_sub) * HW4_ + q;

    float4 acc = make_float4(0.f, 0.f, 0.f, 0.f);
    #pragma unroll 8
    for (int k = 0; k < KITER; k++) {
        const float4 v = f4[base + (size_t)k * CSUB * HW4_];
        const float  s = ws[c_sub + k * CSUB];
        acc.x = fmaf(s, v.x, acc.x);
        acc.y = fmaf(s, v.y, acc.y);
        acc.z = fmaf(s, v.z, acc.z);
        acc.w = fmaf(s, v.w, acc.w);
    }
    sred[tid] = acc;
    __syncthreads();

    // reduce 8 c-lanes -> partial heat; threads 0..47 write one float4 each
    if (tid < HW4_) {
        float4 t = sred[tid];
        #pragma unroll
        for (int cs = 1; cs < CSUB; cs++) {
            const float4 u = sred[cs * HW4_ + tid];
            t.x += u.x; t.y += u.y; t.z += u.z; t.w += u.w;
        }
        float4* gp4 = reinterpret_cast<float4*>(g_part);
        gp4[((size_t)b * GSUB + sub) * HW4_ + tid] = t;
    }
    __syncthreads();

    // ---------------- Group barrier (monotonic ticket) ---------------------
    if (tid == 0) {
        __threadfence();                                  // publish g_part
        const int old = atomicAdd(&g_cnt[b], 1);          // arrive
        const int target = (old & ~3) + 4;                // this replay's goal
        s_target = target;
        volatile int* cnt = &g_cnt[b];
        while (*cnt < target)
            __nanosleep(64);
        __threadfence();                                  // acquire g_part
    }
    __syncthreads();

    // ---------------- Sum partials + normalize (redundant per CTA) ---------
    float4 sv;
    {
        const float4* gp4 = reinterpret_cast<const float4*>(g_part);
        sv = gp4[((size_t)b * GSUB + 0) * HW4_ + q];
        #pragma unroll
        for (int s2 = 1; s2 < GSUB; s2++) {
            const float4 u = gp4[((size_t)b * GSUB + s2) * HW4_ + q];
            sv.x += u.x; sv.y += u.y; sv.z += u.z; sv.w += u.w;
        }
    }

    // block min/max over all 384 threads (values duplicated 8x -- harmless)
    float mn = fminf(fminf(sv.x, sv.y), fminf(sv.z, sv.w));
    float mx = fmaxf(fmaxf(sv.x, sv.y), fmaxf(sv.z, sv.w));
    #pragma unroll
    for (int off = 16; off > 0; off >>= 1) {
        mn = fminf(mn, __shfl_down_sync(0xffffffffu, mn, off));
        mx = fmaxf(mx, __shfl_down_sync(0xffffffffu, mx, off));
    }
    const int warp = tid >> 5, lane = tid & 31;
    if (lane == 0) { smn[warp] = mn; smx[warp] = mx; }
    __syncthreads();
    if (tid == 0) {
        float m0 = smn[0], m1 = smx[0];
        #pragma unroll
        for (int i = 1; i < 12; i++) {
            m0 = fminf(m0, smn[i]);
            m1 = fmaxf(m1, smx[i]);
        }
        s_bmn = m0; s_bmx = m1;
    }
    __syncthreads();

    float4 hv = sv;
    if (s_bmx != 0.f) {
        const float inv = 1.f / (s_bmx - s_bmn);
        hv.x = (sv.x - s_bmn) * inv;
        hv.y = (sv.y - s_bmn) * inv;
        hv.z = (sv.z - s_bmn) * inv;
        hv.w = (sv.w - s_bmn) * inv;
    }

    // ---------------- Pass 2: scale own slice (L2-hot) ----------------------
    #pragma unroll 8
    for (int k = 0; k < KITER; k++) {
        const size_t idx = base + (size_t)k * CSUB * HW4_;
        float4 v = __ldcs(&f4[idx]);           // evict-first read (last use)
        v.x *= hv.x; v.y *= hv.y; v.z *= hv.z; v.w *= hv.w;
        __stcs(&out4[idx], v);                 // streaming write, keep f in L2
    }
}

// ---------------------------------------------------------------------------
extern "C" void kernel_launch(void* const* d_in, const int* in_sizes, int n_in,
                              void* d_out, int out_size)
{
    // Resolve inputs by element count:
    //   features_map      : 25,165,824
    //   classifier_weight :  1,538,048
    //   pids              : 64
    const float* f = nullptr;
    const float* w = nullptr;
    const int*   p = nullptr;
    for (int i = 0; i < n_in; i++) {
        if      (in_sizes[i] == 25165824) f = (const float*)d_in[i];
        else if (in_sizes[i] == 1538048)  w = (const float*)d_in[i];
        else if (in_sizes[i] == 64)       p = (const int*)d_in[i];
    }
    float* out = (float*)d_out;

    fused_kernel<<<B_ * GSUB, NTHR>>>((const float4*)f, w, p, (float4*)out);
}

// round 7
// speedup vs baseline: 1.3356x; 1.3356x over previous
#include <cuda_runtime.h>
#include <cuda_bf16.h>
#include <cstdint>

// Problem constants
#define B_  64
#define C_  2048
#define HW_ 192            // 24 * 8
#define HW4_ 48            // HW_/4 float4s per row
#define NCHUNK 32          // C chunks  (grid = 64*32 = 2048 blocks)
#define CCHUNK (C_ / NCHUNK)   // 64 channels per chunk
#define NPART (NCHUNK * 4)     // 128 partials per (b,hw)
#define NUM_IDS_ 751

// Scratch (__device__ globals; no allocation allowed)
__device__ float g_partial[B_ * NPART * HW_];    // [b][part][hw]  (6 MB)
__device__ float g_heat[B_ * HW_];               // normalized heat

// ---------------------------------------------------------------------------
// pid loader: pids buffer may be int32 (64 ints) or int64 (64 longs).
// Only the first 64 int32 words are read (256 B, safe under both layouts).
// int64 layout => odd words all 0 (values < 751); int32 => odd words random.
// ---------------------------------------------------------------------------
__device__ __forceinline__ int load_pid(const int* __restrict__ p32, int b)
{
    bool odd_all_zero = true;
    bool any_nonzero  = false;
    #pragma unroll
    for (int i = 0; i < 64; i += 2) {
        if (p32[i + 1] != 0) odd_all_zero = false;
        if (p32[i]     != 0) any_nonzero = true;
    }
    const bool is64 = odd_all_zero && any_nonzero;
    int pid = is64 ? p32[2 * b] : p32[b];
    if (pid < 0) pid = 0;
    if (pid >= NUM_IDS_) pid = NUM_IDS_ - 1;
    return pid;
}

// ---------------------------------------------------------------------------
// Kernel 1: partial heat with float4 row loads (default cache policy so f
// populates L2 for the scale kernel's re-read).
// grid = (B_, NCHUNK), block = 192 threads = 4 c-lanes x 48 float4-lanes.
// ---------------------------------------------------------------------------
__global__ void __launch_bounds__(HW_) heat_partial_kernel(
    const float4* __restrict__ f4,
    const float*  __restrict__ w,
    const int*    __restrict__ pids32)
{
    const int b     = blockIdx.x;
    const int chunk = blockIdx.y;
    const int tid   = threadIdx.x;
    const int c_sub = tid / HW4_;   // 0..3
    const int q     = tid % HW4_;   // 0..47 (float4 index within row)

    __shared__ float ws[CCHUNK];
    __shared__ int s_pid;

    if (tid == 0)
        s_pid = load_pid(pids32, b);
    __syncthreads();

    const float* wrow = w + (size_t)s_pid * C_ + chunk * CCHUNK;
    if (tid < CCHUNK)
        ws[tid] = wrow[tid];
    __syncthreads();

    const float4* fb = f4 + ((size_t)b * C_ + (size_t)chunk * CCHUNK) * HW4_ + q;

    float4 acc = make_float4(0.f, 0.f, 0.f, 0.f);
    #pragma unroll
    for (int c = c_sub; c < CCHUNK; c += 4) {
        const float4 v = fb[(size_t)c * HW4_];
        const float  s = ws[c];
        acc.x = fmaf(s, v.x, acc.x);
        acc.y = fmaf(s, v.y, acc.y);
        acc.z = fmaf(s, v.z, acc.z);
        acc.w = fmaf(s, v.w, acc.w);
    }

    const int part = chunk * 4 + c_sub;   // 0..127
    float4* gp4 = reinterpret_cast<float4*>(g_partial);
    // evict-first: partials are consumed once by heat_norm; don't evict f
    __stcs(&gp4[((size_t)b * NPART + part) * HW4_ + q], acc);
}

// ---------------------------------------------------------------------------
// Kernel 2: reduce 128 partials, min/max-normalize per b. grid = B_, block=192.
// ---------------------------------------------------------------------------
__global__ void __launch_bounds__(HW_) heat_norm_kernel()
{
    const int b  = blockIdx.x;
    const int hw = threadIdx.x;

    float s0 = 0.f, s1 = 0.f, s2 = 0.f, s3 = 0.f;
    #pragma unroll
    for (int p = 0; p < NPART; p += 4) {
        s0 += __ldcs(&g_partial[((size_t)b * NPART + p + 0) * HW_ + hw]);
        s1 += __ldcs(&g_partial[((size_t)b * NPART + p + 1) * HW_ + hw]);
        s2 += __ldcs(&g_partial[((size_t)b * NPART + p + 2) * HW_ + hw]);
        s3 += __ldcs(&g_partial[((size_t)b * NPART + p + 3) * HW_ + hw]);
    }
    const float s = (s0 + s1) + (s2 + s3);

    // block min/max over 192 values (6 warps)
    float mn = s, mx = s;
    #pragma unroll
    for (int off = 16; off > 0; off >>= 1) {
        mn = fminf(mn, __shfl_down_sync(0xffffffffu, mn, off));
        mx = fmaxf(mx, __shfl_down_sync(0xffffffffu, mx, off));
    }
    __shared__ float smn[6], smx[6];
    __shared__ float bmn, bmx;
    const int warp = hw >> 5, lane = hw & 31;
    if (lane == 0) { smn[warp] = mn; smx[warp] = mx; }
    __syncthreads();
    if (hw == 0) {
        float m0 = smn[0], m1 = smx[0];
        #pragma unroll
        for (int i = 1; i < 6; i++) {
            m0 = fminf(m0, smn[i]);
            m1 = fmaxf(m1, smx[i]);
        }
        bmn = m0; bmx = m1;
    }
    __syncthreads();

    float h = s;
    if (bmx != 0.f)
        h = (s - bmn) / (bmx - bmn);
    g_heat[(size_t)b * HW_ + hw] = h;
}

// ---------------------------------------------------------------------------
// Kernel 3: out = f * heat[b][hw], float4 + ILP4.
// f should be largely L2-resident from kernel 1 (100 MB < 126 MB L2).
// __ldcs on f: last use, evict-first.  __stcs on out: stream to DRAM without
// evicting the f lines the tail of the kernel still needs.
// ---------------------------------------------------------------------------
#define SC_ILP 4
__global__ void __launch_bounds__(256) scale_kernel(
    const float4* __restrict__ f4,
    float4* __restrict__ out4)
{
    const int base = blockIdx.x * (256 * SC_ILP) + threadIdx.x;

    float4 v[SC_ILP];
    float4 hv[SC_ILP];
    #pragma unroll
    for (int k = 0; k < SC_ILP; k++) {
        const int i  = base + k * 256;
        const int e  = i * 4;            // element index (max 25.2M, fits int32)
        const int hw = e % HW_;          // 4-aligned
        const int b  = e / (C_ * HW_);
        v[k]  = __ldcs(&f4[i]);
        hv[k] = *reinterpret_cast<const float4*>(&g_heat[b * HW_ + hw]);
    }
    #pragma unroll
    for (int k = 0; k < SC_ILP; k++) {
        const int i = base + k * 256;
        float4 r;
        r.x = v[k].x * hv[k].x;
        r.y = v[k].y * hv[k].y;
        r.z = v[k].z * hv[k].z;
        r.w = v[k].w * hv[k].w;
        __stcs(&out4[i], r);
    }
}

// ---------------------------------------------------------------------------
extern "C" void kernel_launch(void* const* d_in, const int* in_sizes, int n_in,
                              void* d_out, int out_size)
{
    // Resolve inputs by element count:
    //   features_map      : 25,165,824
    //   classifier_weight :  1,538,048
    //   pids              : 64
    const float* f = nullptr;
    const float* w = nullptr;
    const int*   p = nullptr;
    for (int i = 0; i < n_in; i++) {
        if      (in_sizes[i] == 25165824) f = (const float*)d_in[i];
        else if (in_sizes[i] == 1538048)  w = (const float*)d_in[i];
        else if (in_sizes[i] == 64)       p = (const int*)d_in[i];
    }
    float* out = (float*)d_out;

    heat_partial_kernel<<<dim3(B_, NCHUNK), HW_>>>((const float4*)f, w, p);
    heat_norm_kernel<<<B_, HW_>>>();

    const int n4 = (B_ * C_ * HW_) / 4;                  // 6,291,456
    const int blocks = n4 / (256 * SC_ILP);              // 6144 (exact)
    scale_kernel<<<blocks, 256>>>((const float4*)f, (float4*)out);
}